// round 15
// baseline (speedup 1.0000x reference)
#include <cuda_runtime.h>
#include <math.h>

// Problem constants
#define Bc 16
#define Ac 3
#define Cc 80
#define Hc 76
#define Wc 76
#define Tc 50
#define Sc (Hc * Wc)            // 5776 (divisible by 4)
#define NCELL (Bc * Ac * Sc)    // 277248
#define NCH 85
#define NT (Bc * Tc)            // 800 targets
#define NSL (NT * 3)            // 2400 suppression-list slots (fixed mapping)

#define TPB 256
#define NWARPS (TPB / 32)
#define NQ (NCELL / 4)          // 69312 float4 cells
#define NBCELL 271              // cell-sweep blocks (271*256*4 = 277504 >= NCELL)
#define NBT (NBCELL + 1)        // +1 build-only block (block 0)

#define EBLK0 1                 // entry warps in blocks [1, 100]
#define CBLK0 101               // corrections in blocks [101, 110]

#define KINV 0xFFFFFFFFu

// ---------------------------------------------------------------------------
// Scratch (device globals, no allocation)
// ---------------------------------------------------------------------------
__device__ unsigned g_sclist[NSL];    // suppressed cell ids (deduped) or KINV
__device__ int      g_nsup;           // count of unique suppressed cells
__device__ unsigned g_ekey[NT];       // (cell<<7)|cls, or KINV
__device__ unsigned g_eflag[NT];      // bit0 = winner, bit1 = first (cell,cls)
__device__ float4   g_evals[NT];      // tx,ty,tw,th
__device__ float    g_part[NBT * 8];  // per-block partials
__device__ unsigned g_gate = 0;       // build-done flag (reset at end)
__device__ unsigned g_done = 0;       // ticket (reset at end)

// softplus via MUFU intrinsics. bce(sigmoid(x), t) == softplus(x) - t*x
// (reference clip(-100) unreachable for finite normal logits).
__device__ __forceinline__ float softplusf(float x) {
    return fmaxf(x, 0.0f) + __logf(1.0f + __expf(-fabsf(x)));
}

// ---------------------------------------------------------------------------
// Single fused kernel, 272 blocks (one resident wave; launch_bounds(256,2)).
//  Block 0:      BUILD ONLY -> fence -> gate. Writes zero partials.
//  Blocks 1..271: unmasked conf sweep (gate-independent!) -> gate ->
//                 corrections (101..110) + entry warps (1..100) ->
//                 8-slot deterministic reduce -> last-block ticket.
// Slots: 0=conf_noobj_sum 1=x 2=y 3=w 4=h 5=conf_obj 6=cls 7=n_mask
// ---------------------------------------------------------------------------
__global__ void __launch_bounds__(TPB, 2) yolo_fused_kernel(
        const float* __restrict__ inp, const float* __restrict__ tgt,
        float* __restrict__ out, int out_size) {
    int tid  = threadIdx.x;
    int lane = tid & 31;
    int wid  = tid >> 5;
    int bx   = blockIdx.x;

    float v[8];
    #pragma unroll
    for (int k = 0; k < 8; k++) v[k] = 0.0f;

    if (bx == 0) {
        // ========================= BUILD =========================
        __shared__ float    s[NT * 5];      // 16 KB staged targets
        __shared__ unsigned skey[NT];       // (cell<<7)|cls or KINV
        __shared__ unsigned spos[NT];       // supmask(3b)<<13 | pos(13b)
        __shared__ int      ssup;

        if (tid == 0) ssup = 0;
        for (int i = tid; i < NT * 5; i += TPB) s[i] = tgt[i];
        __syncthreads();

        // SA = ANCHORS / (608/76) = ANCHORS / 8 (exact in binary)
        const float aw[3] = {1.25f, 2.0f, 4.125f};
        const float ah[3] = {1.625f, 3.75f, 2.875f};

        // phase B: per-target compute (parallel, order-free)
        for (int e = tid; e < NT; e += TPB) {
            int b = e / Tc;
            const float* r = s + e * 5;
            float c0 = r[0], c1 = r[1], c2 = r[2], c3 = r[3], c4 = r[4];
            unsigned key = KINV;
            unsigned posrec = 0u;
            float4 tv = make_float4(0.f, 0.f, 0.f, 0.f);

            if ((c0 + c1 + c2 + c3 + c4) != 0.0f) {     // valid
                int   cls = (int)c0;
                float gx = c1 * (float)Wc;
                float gy = c2 * (float)Hc;
                float gw = c3 * (float)Wc;
                float gh = c4 * (float)Hc;
                int gi = (int)gx;
                int gj = (int)gy;

                // IoU vs anchors (+1 shift), first-max-wins argmax
                float a1 = (gw + 1.0f) * (gh + 1.0f);
                float iou[3];
                int best = 0;
                #pragma unroll
                for (int a = 0; a < 3; a++) {
                    float iw = fmaxf(fminf(gw, aw[a]) + 1.0f, 0.0f);
                    float ih = fmaxf(fminf(gh, ah[a]) + 1.0f, 0.0f);
                    float inter = iw * ih;
                    float a2 = (aw[a] + 1.0f) * (ah[a] + 1.0f);
                    iou[a] = inter / (a1 + a2 - inter + 1e-16f);
                    if (iou[a] > iou[best]) best = a;
                }

                // suppression candidates (drop-mode flat bounds, as ref)
                unsigned sm = 0u;
                int pos = gj * Wc + gi;                  // aliases exactly like
                #pragma unroll                            // the flat cell formula
                for (int a = 0; a < 3; a++) {
                    if (iou[a] > 0.5f) {
                        long long idx = (long long)(b * Ac + a) * Sc + pos;
                        if (idx >= 0 && idx < NCELL) sm |= (1u << a);
                    }
                }
                if (pos >= 0 && pos < (1 << 13))
                    posrec = (sm << 13) | (unsigned)pos;

                // positive assignment (ok = valid & gj<H & gi<W; drop bounds)
                if (gj < Hc && gi < Wc) {
                    long long cell = (long long)(b * Ac + best) * Sc + pos;
                    if (cell >= 0 && cell < NCELL && cls >= 0 && cls < Cc) {
                        key = ((unsigned)cell << 7) | (unsigned)cls;
                        tv.x = gx - (float)gi;
                        tv.y = gy - (float)gj;
                        tv.z = logf(gw / aw[best] + 1e-16f);
                        tv.w = logf(gh / ah[best] + 1e-16f);
                    }
                }
            }
            skey[e] = key;
            spos[e] = posrec;
            g_evals[e] = tv;                             // single writer per e
        }
        __syncthreads();

        // phase C: winner/first flags + suppression dedup + unique count
        for (int e = tid; e < NT; e += TPB) {
            unsigned k  = skey[e];
            unsigned ps = spos[e];
            unsigned mysup = ps >> 13;
            unsigned mypos = ps & 0x1FFFu;
            int base = (e / Tc) * Tc;
            int b = e / Tc;

            bool win = true, first = true;
            unsigned dupmask = 0u;
            #pragma unroll 5
            for (int t2 = 0; t2 < Tc; t2++) {
                int e2 = base + t2;
                unsigned k2 = skey[e2];
                unsigned p2 = spos[e2];
                if (k != KINV) {
                    bool samecell = (k2 != KINV) && ((k2 >> 7) == (k >> 7));
                    if (e2 > e && samecell) win = false;
                    if (e2 < e && k2 == k)  first = false;
                }
                if (e2 < e && (p2 & 0x1FFFu) == mypos)
                    dupmask |= (p2 >> 13);               // earlier sup bits @pos
            }
            unsigned fl = 0u;
            if (k != KINV)
                fl = (win ? 1u : 0u) | (first ? 2u : 0u);
            g_ekey[e] = k;
            g_eflag[e] = fl;

            int cnt = 0;
            #pragma unroll
            for (int a = 0; a < 3; a++) {
                unsigned cellid = KINV;
                if (((mysup >> a) & 1u) && !((dupmask >> a) & 1u)) {
                    cellid = (unsigned)(b * Ac + a) * Sc + mypos;
                    cnt++;
                }
                g_sclist[e * 3 + a] = cellid;            // every slot written
            }
            if (cnt) atomicAdd(&ssup, cnt);              // int: deterministic
        }
        __syncthreads();
        if (tid == 0) {
            g_nsup = ssup;
            __threadfence();                             // publish build
            *(volatile unsigned*)&g_gate = 1u;           // release gate
        }
        // block 0 contributes zero partials (written below)
    } else {
        // ================== UNMASKED CONF SWEEP (pre-gate) ==================
        int i4 = (bx - 1) * TPB + tid;
        if (i4 < NQ) {
            int cell0 = i4 * 4;
            int g  = cell0 / Sc;
            int hw = cell0 - g * Sc;
            const float4 c4 = *reinterpret_cast<const float4*>(
                inp + (size_t)g * NCH * Sc + 4 * Sc + hw);
            v[0] = softplusf(c4.x) + softplusf(c4.y)
                 + softplusf(c4.z) + softplusf(c4.w);
        }

        // ---- gate ----
        if (tid == 0) {
            while (*(volatile unsigned*)&g_gate == 0u) __nanosleep(32);
        }
        __syncthreads();

        // ---- suppressed-cell corrections (blocks 101..110) ----
        if (bx >= CBLK0 && bx < CBLK0 + 10) {
            int j = (bx - CBLK0) * TPB + tid;
            if (j < NSL) {
                unsigned c = __ldcg(&g_sclist[j]);
                if (c != KINV) {
                    int g  = (int)c / Sc;
                    int hw = (int)c - g * Sc;
                    float x4 = __ldcg(&inp[(size_t)g * NCH * Sc + 4 * Sc + hw]);
                    v[0] -= softplusf(x4);               // remove from noobj sum
                }
            }
        }

        // ---- entry warps (blocks 1..100), one warp per target ----
        if (bx >= EBLK0 && bx < EBLK0 + 100) {
            int we = (bx - EBLK0) * NWARPS + wid;
            if (we < NT) {
                unsigned k = __ldcg(&g_ekey[we]);        // warp-uniform
                if (k != KINV) {
                    unsigned fl = __ldcg(&g_eflag[we]);
                    int cell = (int)(k >> 7);
                    int cls  = (int)(k & 127u);
                    int g  = cell / Sc;
                    int hw = cell - g * Sc;
                    const float* base = inp + (size_t)g * NCH * Sc + hw;

                    if (fl & 1u) {                       // winner
                        #pragma unroll
                        for (int c = lane; c < Cc; c += 32)
                            v[6] += softplusf(base[(5 + c) * Sc]);

                        if (lane == 0) {
                            float4 tv = g_evals[we];
                            float x0 = base[0];
                            float x1 = base[Sc];
                            float x2 = base[2 * Sc];
                            float x3 = base[3 * Sc];
                            float x4 = base[4 * Sc];
                            v[1] += softplusf(x0) - tv.x * x0;
                            v[2] += softplusf(x1) - tv.y * x1;
                            float dw = x2 - tv.z; v[3] += dw * dw;
                            float dh = x3 - tv.w; v[4] += dh * dh;
                            v[5] += softplusf(-x4);      // bce(conf, 1)
                            v[7] += 1.0f;
                        }
                    }
                    if ((fl & 2u) && lane == 1)          // distinct (cell,cls)
                        v[6] -= base[(5 + cls) * Sc];
                }
            }
        }
    }

    // ================== 8-slot deterministic block reduce ==================
    #pragma unroll
    for (int k = 0; k < 8; k++)
        #pragma unroll
        for (int off = 16; off > 0; off >>= 1)
            v[k] += __shfl_down_sync(0xffffffffu, v[k], off);

    __shared__ float swarp[NWARPS][8];
    if (lane == 0)
        #pragma unroll
        for (int k = 0; k < 8; k++) swarp[wid][k] = v[k];
    __syncthreads();

    if (wid == 0) {
        float a[8];
        #pragma unroll
        for (int k = 0; k < 8; k++)
            a[k] = (lane < NWARPS) ? swarp[lane][k] : 0.0f;
        #pragma unroll
        for (int k = 0; k < 8; k++)
            #pragma unroll
            for (int off = 4; off > 0; off >>= 1)
                a[k] += __shfl_down_sync(0xffffffffu, a[k], off);
        if (lane == 0)
            #pragma unroll
            for (int k = 0; k < 8; k++) g_part[bx * 8 + k] = a[k];
    }

    // ---- last-block ticket ----
    __shared__ int is_last;
    __threadfence();
    if (tid == 0) {
        unsigned t = atomicAdd(&g_done, 1u);
        is_last = (t == NBT - 1);
    }
    __syncthreads();

    if (is_last) {
        float a[8];
        #pragma unroll
        for (int k = 0; k < 8; k++) a[k] = 0.0f;
        for (int j = tid; j < NBT; j += TPB)
            #pragma unroll
            for (int k = 0; k < 8; k++) a[k] += __ldcg(&g_part[j * 8 + k]);

        #pragma unroll
        for (int k = 0; k < 8; k++)
            #pragma unroll
            for (int off = 16; off > 0; off >>= 1)
                a[k] += __shfl_down_sync(0xffffffffu, a[k], off);
        if (lane == 0)
            #pragma unroll
            for (int k = 0; k < 8; k++) swarp[wid][k] = a[k];
        __syncthreads();

        if (tid == 0) {
            float tot[8];
            #pragma unroll
            for (int k = 0; k < 8; k++) {
                float t = 0.0f;
                #pragma unroll
                for (int w2 = 0; w2 < NWARPS; w2++) t += swarp[w2][k];
                tot[k] = t;
            }
            // tot: 0=noobj_bce 1=x 2=y 3=w 4=h 5=conf_obj 6=cls 7=n_mask
            const float N = (float)NCELL;
            float n_m  = tot[7];
            float n_nm = (float)(NCELL - g_nsup);
            float loss_x = tot[1] / N / n_m;
            float loss_y = tot[2] / N / n_m;
            float loss_w = tot[3] / N / n_m;
            float loss_h = tot[4] / N / n_m;
            float loss_conf = tot[5] / N / n_m + 0.5f * tot[0] / N / n_nm;
            float loss_cls  = tot[6] / (n_m * (float)Cc) / n_m;
            float loss = 2.5f * (loss_x + loss_y) + 2.5f * (loss_w + loss_h)
                       + loss_conf + loss_cls;
            float res[7] = {loss, loss_x, loss_y, loss_w, loss_h,
                            loss_conf, loss_cls};
            for (int k = 0; k < 7 && k < out_size; k++) out[k] = res[k];

            // reset gate + ticket for the next graph replay
            *(volatile unsigned*)&g_done = 0u;
            *(volatile unsigned*)&g_gate = 0u;
        }
    }
}

// ---------------------------------------------------------------------------
extern "C" void kernel_launch(void* const* d_in, const int* in_sizes, int n_in,
                              void* d_out, int out_size) {
    const float* inp = (const float*)d_in[0];
    const float* tgt = (const float*)d_in[1];
    if (n_in >= 2 && in_sizes[0] < in_sizes[1]) {   // defensive
        const float* tmp = inp; inp = tgt; tgt = tmp;
    }

    yolo_fused_kernel<<<NBT, TPB>>>(inp, tgt, (float*)d_out, out_size);
}

// round 16
// speedup vs baseline: 1.0013x; 1.0013x over previous
#include <cuda_runtime.h>
#include <math.h>

// Problem constants
#define Bc 16
#define Ac 3
#define Cc 80
#define Hc 76
#define Wc 76
#define Tc 50
#define Sc (Hc * Wc)            // 5776 (divisible by 4)
#define NCELL (Bc * Ac * Sc)    // 277248
#define NCH 85
#define NT (Bc * Tc)            // 800 targets
#define NSL (NT * 3)            // 2400 suppression-list slots (fixed mapping)

#define TPB 256
#define NWARPS (TPB / 32)
#define NQ (NCELL / 4)          // 69312 float4 cells
#define NB ((NQ + TPB - 1) / TPB)   // 271 blocks

#define CBLK0 101               // correction blocks [101, 110]

#define BTPB 256
#define KINV 0xFFFFFFFFu

// ---------------------------------------------------------------------------
// Scratch (device globals, no allocation)
// ---------------------------------------------------------------------------
__device__ unsigned g_sclist[NSL];    // suppressed cell ids (deduped) or KINV
__device__ int      g_nsup;           // count of unique suppressed cells
__device__ unsigned g_ekey[NT];       // (cell<<7)|cls, or KINV
__device__ unsigned g_eflag[NT];      // bit0 = winner, bit1 = first (cell,cls)
__device__ float4   g_evals[NT];      // tx,ty,tw,th
__device__ float    g_part[NB * 8];   // per-block partials
__device__ unsigned g_done = 0;       // ticket (reset at end)

// softplus via MUFU intrinsics. bce(sigmoid(x), t) == softplus(x) - t*x
// (reference clip(-100) unreachable for finite normal logits).
__device__ __forceinline__ float softplusf(float x) {
    return fmaxf(x, 0.0f) + __logf(1.0f + __expf(-fabsf(x)));
}

// ---------------------------------------------------------------------------
// Kernel 1: build (R15's verified build, standalone). 1 block x 256 threads.
// No suppression bitmask: emits a fixed-slot deduped suppressed-cell list
// (slot = target*3 + anchor) + unique count. Winner/first flags via
// order-free parallel scan. Single writer per slot => deterministic.
// ---------------------------------------------------------------------------
__global__ void __launch_bounds__(BTPB) yolo_build_kernel(const float* __restrict__ tgt) {
    __shared__ float    s[NT * 5];      // 16 KB staged targets
    __shared__ unsigned skey[NT];       // (cell<<7)|cls or KINV
    __shared__ unsigned spos[NT];       // supmask(3b)<<13 | pos(13b)
    __shared__ int      ssup;

    int tid = threadIdx.x;
    if (tid == 0) ssup = 0;
    for (int i = tid; i < NT * 5; i += BTPB) s[i] = tgt[i];
    __syncthreads();

    // SA = ANCHORS / (608/76) = ANCHORS / 8 (exact in binary)
    const float aw[3] = {1.25f, 2.0f, 4.125f};
    const float ah[3] = {1.625f, 3.75f, 2.875f};

    // phase B: per-target compute (parallel, order-free)
    for (int e = tid; e < NT; e += BTPB) {
        int b = e / Tc;
        const float* r = s + e * 5;
        float c0 = r[0], c1 = r[1], c2 = r[2], c3 = r[3], c4 = r[4];
        unsigned key = KINV;
        unsigned posrec = 0u;
        float4 tv = make_float4(0.f, 0.f, 0.f, 0.f);

        if ((c0 + c1 + c2 + c3 + c4) != 0.0f) {     // valid
            int   cls = (int)c0;
            float gx = c1 * (float)Wc;
            float gy = c2 * (float)Hc;
            float gw = c3 * (float)Wc;
            float gh = c4 * (float)Hc;
            int gi = (int)gx;
            int gj = (int)gy;

            // IoU vs anchors (+1 shift), first-max-wins argmax
            float a1 = (gw + 1.0f) * (gh + 1.0f);
            float iou[3];
            int best = 0;
            #pragma unroll
            for (int a = 0; a < 3; a++) {
                float iw = fmaxf(fminf(gw, aw[a]) + 1.0f, 0.0f);
                float ih = fmaxf(fminf(gh, ah[a]) + 1.0f, 0.0f);
                float inter = iw * ih;
                float a2 = (aw[a] + 1.0f) * (ah[a] + 1.0f);
                iou[a] = inter / (a1 + a2 - inter + 1e-16f);
                if (iou[a] > iou[best]) best = a;
            }

            // suppression candidates (drop-mode flat bounds, as reference)
            unsigned sm = 0u;
            int pos = gj * Wc + gi;
            #pragma unroll
            for (int a = 0; a < 3; a++) {
                if (iou[a] > 0.5f) {
                    long long idx = (long long)(b * Ac + a) * Sc + pos;
                    if (idx >= 0 && idx < NCELL) sm |= (1u << a);
                }
            }
            if (pos >= 0 && pos < (1 << 13))
                posrec = (sm << 13) | (unsigned)pos;

            // positive assignment (ok = valid & gj<H & gi<W; drop bounds)
            if (gj < Hc && gi < Wc) {
                long long cell = (long long)(b * Ac + best) * Sc + pos;
                if (cell >= 0 && cell < NCELL && cls >= 0 && cls < Cc) {
                    key = ((unsigned)cell << 7) | (unsigned)cls;
                    tv.x = gx - (float)gi;
                    tv.y = gy - (float)gj;
                    tv.z = logf(gw / aw[best] + 1e-16f);
                    tv.w = logf(gh / ah[best] + 1e-16f);
                }
            }
        }
        skey[e] = key;
        spos[e] = posrec;
        g_evals[e] = tv;                             // single writer per e
    }
    __syncthreads();

    // phase C: winner/first flags + suppression dedup + unique count
    for (int e = tid; e < NT; e += BTPB) {
        unsigned k  = skey[e];
        unsigned ps = spos[e];
        unsigned mysup = ps >> 13;
        unsigned mypos = ps & 0x1FFFu;
        int base = (e / Tc) * Tc;
        int b = e / Tc;

        bool win = true, first = true;
        unsigned dupmask = 0u;
        #pragma unroll 5
        for (int t2 = 0; t2 < Tc; t2++) {
            int e2 = base + t2;
            unsigned k2 = skey[e2];
            unsigned p2 = spos[e2];
            if (k != KINV) {
                bool samecell = (k2 != KINV) && ((k2 >> 7) == (k >> 7));
                if (e2 > e && samecell) win = false;
                if (e2 < e && k2 == k)  first = false;
            }
            if (e2 < e && (p2 & 0x1FFFu) == mypos)
                dupmask |= (p2 >> 13);               // earlier sup bits @pos
        }
        unsigned fl = 0u;
        if (k != KINV)
            fl = (win ? 1u : 0u) | (first ? 2u : 0u);
        g_ekey[e] = k;
        g_eflag[e] = fl;

        int cnt = 0;
        #pragma unroll
        for (int a = 0; a < 3; a++) {
            unsigned cellid = KINV;
            if (((mysup >> a) & 1u) && !((dupmask >> a) & 1u)) {
                cellid = (unsigned)(b * Ac + a) * Sc + mypos;
                cnt++;
            }
            g_sclist[e * 3 + a] = cellid;            // every slot written
        }
        if (cnt) atomicAdd(&ssup, cnt);              // int add: deterministic
    }
    __syncthreads();
    if (tid == 0) g_nsup = ssup;
}

// ---------------------------------------------------------------------------
// Kernel 2: main (R11 structure, minus the suppression-bitmask load).
//  - Per-thread: UNMASKED float4 conf sweep -> slot 0 (sum over all cells).
//  - Blocks 101..110: subtract softplus at the <=2400 suppressed cells.
//  - Blocks 0..99: one warp per entry (class loop lane-split; lane 0 does
//    x/y/w/h/conf; lane 1 the distinct-(cell,cls) term).
//  - 8-slot deterministic tree reduce + last-block ticket final combine.
// Slots: 0=noobj_sum 1=x 2=y 3=w 4=h 5=conf_obj 6=cls 7=n_mask
// ---------------------------------------------------------------------------
__global__ void __launch_bounds__(TPB) yolo_main_kernel(
        const float* __restrict__ inp, float* __restrict__ out, int out_size) {
    int i4 = blockIdx.x * TPB + threadIdx.x;
    int lane = threadIdx.x & 31;
    int wid  = threadIdx.x >> 5;
    float v[8];
    #pragma unroll
    for (int k = 0; k < 8; k++) v[k] = 0.0f;

    // --- unmasked conf sweep, 4 cells per thread (no sup dependency) ---
    if (i4 < NQ) {
        int cell0 = i4 * 4;
        int g  = cell0 / Sc;
        int hw = cell0 - g * Sc;              // multiple of 4 within channel
        const float4 c4 = *reinterpret_cast<const float4*>(
            inp + (size_t)g * NCH * Sc + 4 * Sc + hw);
        v[0] = softplusf(c4.x) + softplusf(c4.y)
             + softplusf(c4.z) + softplusf(c4.w);
    }

    // --- suppressed-cell corrections (blocks 101..110) ---
    if (blockIdx.x >= CBLK0 && blockIdx.x < CBLK0 + 10) {
        int j = (blockIdx.x - CBLK0) * TPB + threadIdx.x;
        if (j < NSL) {
            unsigned c = g_sclist[j];
            if (c != KINV) {
                int g  = (int)c / Sc;
                int hw = (int)c - g * Sc;
                float x4 = inp[(size_t)g * NCH * Sc + 4 * Sc + hw];
                v[0] -= softplusf(x4);        // remove from noobj sum
            }
        }
    }

    // --- per-entry masked terms: one warp per entry (blocks 0..99) ---
    int we = blockIdx.x * NWARPS + wid;
    if (we < NT) {
        unsigned k = g_ekey[we];              // warp-uniform
        if (k != KINV) {
            unsigned fl = g_eflag[we];
            int cell = (int)(k >> 7);
            int cls  = (int)(k & 127u);
            int g  = cell / Sc;
            int hw = cell - g * Sc;
            const float* base = inp + (size_t)g * NCH * Sc + hw;

            if (fl & 1u) {                    // winner: full cell losses
                #pragma unroll
                for (int c = lane; c < Cc; c += 32)
                    v[6] += softplusf(base[(5 + c) * Sc]);

                if (lane == 0) {
                    float4 tv = g_evals[we];
                    float x0 = base[0];
                    float x1 = base[Sc];
                    float x2 = base[2 * Sc];
                    float x3 = base[3 * Sc];
                    float x4 = base[4 * Sc];
                    v[1] += softplusf(x0) - tv.x * x0;
                    v[2] += softplusf(x1) - tv.y * x1;
                    float dw = x2 - tv.z; v[3] += dw * dw;
                    float dh = x3 - tv.w; v[4] += dh * dh;
                    v[5] += softplusf(-x4);   // bce(conf, 1)
                    v[7] += 1.0f;
                }
            }
            if ((fl & 2u) && lane == 1)       // distinct (cell,cls)
                v[6] -= base[(5 + cls) * Sc];
        }
    }

    // --- deterministic 8-slot block reduce (R11 structure) ---
    #pragma unroll
    for (int k = 0; k < 8; k++)
        #pragma unroll
        for (int off = 16; off > 0; off >>= 1)
            v[k] += __shfl_down_sync(0xffffffffu, v[k], off);

    __shared__ float swarp[NWARPS][8];
    if (lane == 0)
        #pragma unroll
        for (int k = 0; k < 8; k++) swarp[wid][k] = v[k];
    __syncthreads();

    if (wid == 0) {
        float a[8];
        #pragma unroll
        for (int k = 0; k < 8; k++)
            a[k] = (lane < NWARPS) ? swarp[lane][k] : 0.0f;
        #pragma unroll
        for (int k = 0; k < 8; k++)
            #pragma unroll
            for (int off = 4; off > 0; off >>= 1)
                a[k] += __shfl_down_sync(0xffffffffu, a[k], off);
        if (lane == 0)
            #pragma unroll
            for (int k = 0; k < 8; k++) g_part[blockIdx.x * 8 + k] = a[k];
    }

    // --- last-block ticket (threadFenceReduction pattern) ---
    __shared__ int is_last;
    __threadfence();
    if (threadIdx.x == 0) {
        unsigned t = atomicAdd(&g_done, 1u);
        is_last = (t == NB - 1);
        if (is_last) g_done = 0;              // reset for next replay
    }
    __syncthreads();

    if (is_last) {
        float a[8];
        #pragma unroll
        for (int k = 0; k < 8; k++) a[k] = 0.0f;
        for (int j = threadIdx.x; j < NB; j += TPB)
            #pragma unroll
            for (int k = 0; k < 8; k++) a[k] += __ldcg(&g_part[j * 8 + k]);

        #pragma unroll
        for (int k = 0; k < 8; k++)
            #pragma unroll
            for (int off = 16; off > 0; off >>= 1)
                a[k] += __shfl_down_sync(0xffffffffu, a[k], off);
        if (lane == 0)
            #pragma unroll
            for (int k = 0; k < 8; k++) swarp[wid][k] = a[k];
        __syncthreads();

        if (threadIdx.x == 0) {
            float tot[8];
            #pragma unroll
            for (int k = 0; k < 8; k++) {
                float t = 0.0f;
                #pragma unroll
                for (int w2 = 0; w2 < NWARPS; w2++) t += swarp[w2][k];
                tot[k] = t;
            }
            // tot: 0=noobj_bce 1=x 2=y 3=w 4=h 5=conf_obj 6=cls 7=n_mask
            const float N = (float)NCELL;
            float n_m  = tot[7];
            float n_nm = (float)(NCELL - g_nsup);
            float loss_x = tot[1] / N / n_m;
            float loss_y = tot[2] / N / n_m;
            float loss_w = tot[3] / N / n_m;
            float loss_h = tot[4] / N / n_m;
            float loss_conf = tot[5] / N / n_m + 0.5f * tot[0] / N / n_nm;
            float loss_cls  = tot[6] / (n_m * (float)Cc) / n_m;
            float loss = 2.5f * (loss_x + loss_y) + 2.5f * (loss_w + loss_h)
                       + loss_conf + loss_cls;
            float res[7] = {loss, loss_x, loss_y, loss_w, loss_h,
                            loss_conf, loss_cls};
            for (int k = 0; k < 7 && k < out_size; k++) out[k] = res[k];
        }
    }
}

// ---------------------------------------------------------------------------
extern "C" void kernel_launch(void* const* d_in, const int* in_sizes, int n_in,
                              void* d_out, int out_size) {
    const float* inp = (const float*)d_in[0];
    const float* tgt = (const float*)d_in[1];
    if (n_in >= 2 && in_sizes[0] < in_sizes[1]) {   // defensive
        const float* tmp = inp; inp = tgt; tgt = tmp;
    }

    yolo_build_kernel<<<1, BTPB>>>(tgt);
    yolo_main_kernel<<<NB, TPB>>>(inp, (float*)d_out, out_size);
}

// round 17
// speedup vs baseline: 1.3067x; 1.3050x over previous
#include <cuda_runtime.h>
#include <math.h>

// Problem constants
#define Bc 16
#define Ac 3
#define Cc 80
#define Hc 76
#define Wc 76
#define Tc 50
#define Sc (Hc * Wc)            // 5776 (divisible by 4)
#define NCELL (Bc * Ac * Sc)    // 277248
#define NCH 85
#define NT (Bc * Tc)            // 800 targets
#define NSL (NT * 3)            // 2400 suppression-list slots (fixed mapping)

#define TPB 256
#define NWARPS (TPB / 32)
#define NQ (NCELL / 4)          // 69312 float4 cells
#define NB ((NQ + TPB - 1) / TPB)   // 271 blocks

#define CBLK0 101               // correction blocks [101, 110]

#define BTPB 800                // build: ONE THREAD PER TARGET (R11 shape)
#define KINV 0xFFFFFFFFu

// ---------------------------------------------------------------------------
// Scratch (device globals, no allocation)
// ---------------------------------------------------------------------------
__device__ unsigned g_sclist[NSL];    // suppressed cell ids (deduped) or KINV
__device__ int      g_nsup;           // count of unique suppressed cells
__device__ unsigned g_ekey[NT];       // (cell<<7)|cls, or KINV
__device__ unsigned g_eflag[NT];      // bit0 = winner, bit1 = first (cell,cls)
__device__ float4   g_evals[NT];      // tx,ty,tw,th
__device__ float    g_part[NB * 8];   // per-block partials
__device__ unsigned g_done = 0;       // ticket (reset at end)

// softplus via MUFU intrinsics. bce(sigmoid(x), t) == softplus(x) - t*x
// (reference clip(-100) unreachable for finite normal logits).
__device__ __forceinline__ float softplusf(float x) {
    return fmaxf(x, 0.0f) + __logf(1.0f + __expf(-fabsf(x)));
}

// ---------------------------------------------------------------------------
// Kernel 1: build. One block, 800 threads — ONE THREAD PER TARGET (the R11
// shape that measured ~2 us). Same outputs as R16: fixed-slot deduped
// suppressed-cell list + unique count, winner/first flags, entry records.
// Single writer per slot => deterministic.
// ---------------------------------------------------------------------------
__global__ void __launch_bounds__(BTPB) yolo_build_kernel(const float* __restrict__ tgt) {
    __shared__ float    s[NT * 5];      // 16 KB staged targets
    __shared__ unsigned skey[NT];       // (cell<<7)|cls or KINV
    __shared__ unsigned spos[NT];       // supmask(3b)<<13 | pos(13b)
    __shared__ int      ssup;

    int e = threadIdx.x;                // target index, 0..799
    if (e == 0) ssup = 0;
    for (int i = e; i < NT * 5; i += BTPB) s[i] = tgt[i];
    __syncthreads();

    // SA = ANCHORS / (608/76) = ANCHORS / 8 (exact in binary)
    const float aw[3] = {1.25f, 2.0f, 4.125f};
    const float ah[3] = {1.625f, 3.75f, 2.875f};

    // phase B: per-target compute (fully parallel, depth 1)
    {
        int b = e / Tc;
        const float* r = s + e * 5;
        float c0 = r[0], c1 = r[1], c2 = r[2], c3 = r[3], c4 = r[4];
        unsigned key = KINV;
        unsigned posrec = 0u;
        float4 tv = make_float4(0.f, 0.f, 0.f, 0.f);

        if ((c0 + c1 + c2 + c3 + c4) != 0.0f) {     // valid
            int   cls = (int)c0;
            float gx = c1 * (float)Wc;
            float gy = c2 * (float)Hc;
            float gw = c3 * (float)Wc;
            float gh = c4 * (float)Hc;
            int gi = (int)gx;
            int gj = (int)gy;

            // IoU vs anchors (+1 shift), first-max-wins argmax
            float a1 = (gw + 1.0f) * (gh + 1.0f);
            float iou[3];
            int best = 0;
            #pragma unroll
            for (int a = 0; a < 3; a++) {
                float iw = fmaxf(fminf(gw, aw[a]) + 1.0f, 0.0f);
                float ih = fmaxf(fminf(gh, ah[a]) + 1.0f, 0.0f);
                float inter = iw * ih;
                float a2 = (aw[a] + 1.0f) * (ah[a] + 1.0f);
                iou[a] = inter / (a1 + a2 - inter + 1e-16f);
                if (iou[a] > iou[best]) best = a;
            }

            // suppression candidates (drop-mode flat bounds, as reference)
            unsigned sm = 0u;
            int pos = gj * Wc + gi;
            #pragma unroll
            for (int a = 0; a < 3; a++) {
                if (iou[a] > 0.5f) {
                    long long idx = (long long)(b * Ac + a) * Sc + pos;
                    if (idx >= 0 && idx < NCELL) sm |= (1u << a);
                }
            }
            if (pos >= 0 && pos < (1 << 13))
                posrec = (sm << 13) | (unsigned)pos;

            // positive assignment (ok = valid & gj<H & gi<W; drop bounds)
            if (gj < Hc && gi < Wc) {
                long long cell = (long long)(b * Ac + best) * Sc + pos;
                if (cell >= 0 && cell < NCELL && cls >= 0 && cls < Cc) {
                    key = ((unsigned)cell << 7) | (unsigned)cls;
                    tv.x = gx - (float)gi;
                    tv.y = gy - (float)gj;
                    tv.z = logf(gw / aw[best] + 1e-16f);
                    tv.w = logf(gh / ah[best] + 1e-16f);
                }
            }
        }
        skey[e] = key;
        spos[e] = posrec;
        g_evals[e] = tv;                             // single writer per e
    }
    __syncthreads();

    // phase C: winner/first flags + suppression dedup + unique count
    // (one 50-iteration SMEM scan per thread, parallel across 800 threads)
    {
        unsigned k  = skey[e];
        unsigned ps = spos[e];
        unsigned mysup = ps >> 13;
        unsigned mypos = ps & 0x1FFFu;
        int base = (e / Tc) * Tc;
        int b = e / Tc;

        bool win = true, first = true;
        unsigned dupmask = 0u;
        #pragma unroll 5
        for (int t2 = 0; t2 < Tc; t2++) {
            int e2 = base + t2;
            unsigned k2 = skey[e2];
            unsigned p2 = spos[e2];
            if (k != KINV) {
                bool samecell = (k2 != KINV) && ((k2 >> 7) == (k >> 7));
                if (e2 > e && samecell) win = false;
                if (e2 < e && k2 == k)  first = false;
            }
            if (e2 < e && (p2 & 0x1FFFu) == mypos)
                dupmask |= (p2 >> 13);               // earlier sup bits @pos
        }
        unsigned fl = 0u;
        if (k != KINV)
            fl = (win ? 1u : 0u) | (first ? 2u : 0u);
        g_ekey[e] = k;
        g_eflag[e] = fl;

        int cnt = 0;
        #pragma unroll
        for (int a = 0; a < 3; a++) {
            unsigned cellid = KINV;
            if (((mysup >> a) & 1u) && !((dupmask >> a) & 1u)) {
                cellid = (unsigned)(b * Ac + a) * Sc + mypos;
                cnt++;
            }
            g_sclist[e * 3 + a] = cellid;            // every slot written
        }
        if (cnt) atomicAdd(&ssup, cnt);              // int add: deterministic
    }
    __syncthreads();
    if (e == 0) g_nsup = ssup;
}

// ---------------------------------------------------------------------------
// Kernel 2: main — UNCHANGED from R16 (measured 10.5 us).
//  - Per-thread: unmasked float4 conf sweep -> slot 0.
//  - Blocks 101..110: subtract softplus at the <=2400 suppressed cells.
//  - Blocks 0..99: one warp per entry.
//  - 8-slot deterministic tree reduce + last-block ticket final combine.
// Slots: 0=noobj_sum 1=x 2=y 3=w 4=h 5=conf_obj 6=cls 7=n_mask
// ---------------------------------------------------------------------------
__global__ void __launch_bounds__(TPB) yolo_main_kernel(
        const float* __restrict__ inp, float* __restrict__ out, int out_size) {
    int i4 = blockIdx.x * TPB + threadIdx.x;
    int lane = threadIdx.x & 31;
    int wid  = threadIdx.x >> 5;
    float v[8];
    #pragma unroll
    for (int k = 0; k < 8; k++) v[k] = 0.0f;

    // --- unmasked conf sweep, 4 cells per thread (no sup dependency) ---
    if (i4 < NQ) {
        int cell0 = i4 * 4;
        int g  = cell0 / Sc;
        int hw = cell0 - g * Sc;              // multiple of 4 within channel
        const float4 c4 = *reinterpret_cast<const float4*>(
            inp + (size_t)g * NCH * Sc + 4 * Sc + hw);
        v[0] = softplusf(c4.x) + softplusf(c4.y)
             + softplusf(c4.z) + softplusf(c4.w);
    }

    // --- suppressed-cell corrections (blocks 101..110) ---
    if (blockIdx.x >= CBLK0 && blockIdx.x < CBLK0 + 10) {
        int j = (blockIdx.x - CBLK0) * TPB + threadIdx.x;
        if (j < NSL) {
            unsigned c = g_sclist[j];
            if (c != KINV) {
                int g  = (int)c / Sc;
                int hw = (int)c - g * Sc;
                float x4 = inp[(size_t)g * NCH * Sc + 4 * Sc + hw];
                v[0] -= softplusf(x4);        // remove from noobj sum
            }
        }
    }

    // --- per-entry masked terms: one warp per entry (blocks 0..99) ---
    int we = blockIdx.x * NWARPS + wid;
    if (we < NT) {
        unsigned k = g_ekey[we];              // warp-uniform
        if (k != KINV) {
            unsigned fl = g_eflag[we];
            int cell = (int)(k >> 7);
            int cls  = (int)(k & 127u);
            int g  = cell / Sc;
            int hw = cell - g * Sc;
            const float* base = inp + (size_t)g * NCH * Sc + hw;

            if (fl & 1u) {                    // winner: full cell losses
                #pragma unroll
                for (int c = lane; c < Cc; c += 32)
                    v[6] += softplusf(base[(5 + c) * Sc]);

                if (lane == 0) {
                    float4 tv = g_evals[we];
                    float x0 = base[0];
                    float x1 = base[Sc];
                    float x2 = base[2 * Sc];
                    float x3 = base[3 * Sc];
                    float x4 = base[4 * Sc];
                    v[1] += softplusf(x0) - tv.x * x0;
                    v[2] += softplusf(x1) - tv.y * x1;
                    float dw = x2 - tv.z; v[3] += dw * dw;
                    float dh = x3 - tv.w; v[4] += dh * dh;
                    v[5] += softplusf(-x4);   // bce(conf, 1)
                    v[7] += 1.0f;
                }
            }
            if ((fl & 2u) && lane == 1)       // distinct (cell,cls)
                v[6] -= base[(5 + cls) * Sc];
        }
    }

    // --- deterministic 8-slot block reduce ---
    #pragma unroll
    for (int k = 0; k < 8; k++)
        #pragma unroll
        for (int off = 16; off > 0; off >>= 1)
            v[k] += __shfl_down_sync(0xffffffffu, v[k], off);

    __shared__ float swarp[NWARPS][8];
    if (lane == 0)
        #pragma unroll
        for (int k = 0; k < 8; k++) swarp[wid][k] = v[k];
    __syncthreads();

    if (wid == 0) {
        float a[8];
        #pragma unroll
        for (int k = 0; k < 8; k++)
            a[k] = (lane < NWARPS) ? swarp[lane][k] : 0.0f;
        #pragma unroll
        for (int k = 0; k < 8; k++)
            #pragma unroll
            for (int off = 4; off > 0; off >>= 1)
                a[k] += __shfl_down_sync(0xffffffffu, a[k], off);
        if (lane == 0)
            #pragma unroll
            for (int k = 0; k < 8; k++) g_part[blockIdx.x * 8 + k] = a[k];
    }

    // --- last-block ticket (threadFenceReduction pattern) ---
    __shared__ int is_last;
    __threadfence();
    if (threadIdx.x == 0) {
        unsigned t = atomicAdd(&g_done, 1u);
        is_last = (t == NB - 1);
        if (is_last) g_done = 0;              // reset for next replay
    }
    __syncthreads();

    if (is_last) {
        float a[8];
        #pragma unroll
        for (int k = 0; k < 8; k++) a[k] = 0.0f;
        for (int j = threadIdx.x; j < NB; j += TPB)
            #pragma unroll
            for (int k = 0; k < 8; k++) a[k] += __ldcg(&g_part[j * 8 + k]);

        #pragma unroll
        for (int k = 0; k < 8; k++)
            #pragma unroll
            for (int off = 16; off > 0; off >>= 1)
                a[k] += __shfl_down_sync(0xffffffffu, a[k], off);
        if (lane == 0)
            #pragma unroll
            for (int k = 0; k < 8; k++) swarp[wid][k] = a[k];
        __syncthreads();

        if (threadIdx.x == 0) {
            float tot[8];
            #pragma unroll
            for (int k = 0; k < 8; k++) {
                float t = 0.0f;
                #pragma unroll
                for (int w2 = 0; w2 < NWARPS; w2++) t += swarp[w2][k];
                tot[k] = t;
            }
            // tot: 0=noobj_bce 1=x 2=y 3=w 4=h 5=conf_obj 6=cls 7=n_mask
            const float N = (float)NCELL;
            float n_m  = tot[7];
            float n_nm = (float)(NCELL - g_nsup);
            float loss_x = tot[1] / N / n_m;
            float loss_y = tot[2] / N / n_m;
            float loss_w = tot[3] / N / n_m;
            float loss_h = tot[4] / N / n_m;
            float loss_conf = tot[5] / N / n_m + 0.5f * tot[0] / N / n_nm;
            float loss_cls  = tot[6] / (n_m * (float)Cc) / n_m;
            float loss = 2.5f * (loss_x + loss_y) + 2.5f * (loss_w + loss_h)
                       + loss_conf + loss_cls;
            float res[7] = {loss, loss_x, loss_y, loss_w, loss_h,
                            loss_conf, loss_cls};
            for (int k = 0; k < 7 && k < out_size; k++) out[k] = res[k];
        }
    }
}

// ---------------------------------------------------------------------------
extern "C" void kernel_launch(void* const* d_in, const int* in_sizes, int n_in,
                              void* d_out, int out_size) {
    const float* inp = (const float*)d_in[0];
    const float* tgt = (const float*)d_in[1];
    if (n_in >= 2 && in_sizes[0] < in_sizes[1]) {   // defensive
        const float* tmp = inp; inp = tgt; tgt = tmp;
    }

    yolo_build_kernel<<<1, BTPB>>>(tgt);
    yolo_main_kernel<<<NB, TPB>>>(inp, (float*)d_out, out_size);
}